// round 13
// baseline (speedup 1.0000x reference)
#include <cuda_runtime.h>
#include <cuda_fp16.h>
#include <cstdint>
#include <math.h>

// Problem constants
#define Bz 2
#define Sq 2048
#define Ed 1024
#define Hh 16
#define Dh 64
#define E3 3072
#define Mrows (Bz*Sq)   // 4096

// score domain: y = (q.k) * 0.125 * log2(e); folded into Q at GEMM epilogue
#define QSCALE 0.18033688011112042f
#define MASKC  1.4426950408889634e-9f   // 1e-9 * log2(e)

// ---------------- device scratch ----------------
__device__ __align__(16) __half g_xh [Bz * Sq * Ed];
__device__ __align__(16) __half g_wh [E3 * Ed];
__device__ __align__(16) __half g_w2h[Ed * Ed];
__device__ __align__(16) __half g_qh2[Bz * Sq * Ed];
__device__ __align__(16) __half g_kh2[Bz * Sq * Ed];
__device__ __align__(16) __half g_vh [Bz * Sq * Ed];
__device__ __align__(16) __half g_ctxh[Bz * Sq * Ed];
__device__ __align__(16) unsigned long long g_mbits[(size_t)Bz * Sq * Sq / 64];

// ---------------- base-PTX helpers ----------------
__device__ __forceinline__ uint32_t smem_u32(const void* p) {
    uint32_t a;
    asm("{ .reg .u64 t; cvta.to.shared.u64 t, %1; cvt.u32.u64 %0, t; }" : "=r"(a) : "l"(p));
    return a;
}
__device__ __forceinline__ void cp_async16(uint32_t dst, const void* src) {
    asm volatile("cp.async.cg.shared.global [%0], [%1], 16;" :: "r"(dst), "l"(src));
}
#define CP_COMMIT() asm volatile("cp.async.commit_group;" ::: "memory")
#define CP_WAIT(n)  asm volatile("cp.async.wait_group %0;" :: "n"(n) : "memory")

__device__ __forceinline__ void mma_f16(float* d, const uint32_t* a, uint32_t b0, uint32_t b1) {
    asm volatile("mma.sync.aligned.m16n8k16.row.col.f32.f16.f16.f32 "
                 "{%0,%1,%2,%3}, {%4,%5,%6,%7}, {%8,%9}, {%0,%1,%2,%3};"
                 : "+f"(d[0]), "+f"(d[1]), "+f"(d[2]), "+f"(d[3])
                 : "r"(a[0]), "r"(a[1]), "r"(a[2]), "r"(a[3]), "r"(b0), "r"(b1));
}
__device__ __forceinline__ uint32_t pack_h2(float lo, float hi) {
    uint32_t r; asm("cvt.rn.f16x2.f32 %0, %1, %2;" : "=r"(r) : "f"(hi), "f"(lo)); return r;
}
__device__ __forceinline__ uint32_t ex2_h2(uint32_t y) {
    uint32_t r; asm("ex2.approx.f16x2 %0, %1;" : "=r"(r) : "r"(y)); return r;
}
#define LDM_X4(r0, r1, r2, r3, addr) \
    asm volatile("ldmatrix.sync.aligned.m8n8.x4.shared.b16 {%0,%1,%2,%3}, [%4];" \
                 : "=r"(r0), "=r"(r1), "=r"(r2), "=r"(r3) : "r"(addr))
#define LDM_X4_T(r0, r1, r2, r3, addr) \
    asm volatile("ldmatrix.sync.aligned.m8n8.x4.trans.shared.b16 {%0,%1,%2,%3}, [%4];" \
                 : "=r"(r0), "=r"(r1), "=r"(r2), "=r"(r3) : "r"(addr))

// ---------------- fused prep kernel (proven R10) ----------------------------
#define F2H_BLKS 4096
#define TRW_BLKS 3072
#define TRF_BLKS 1024
#define PACK_BLKS 512
#define PREP_BLKS (F2H_BLKS + TRW_BLKS + TRF_BLKS + PACK_BLKS)

__global__ void prep_all_kernel(const float4* __restrict__ x,
                                const float* __restrict__ wk,
                                const float* __restrict__ fck,
                                const void* __restrict__ mask,
                                uint2* __restrict__ xh,
                                __half* __restrict__ wh,
                                __half* __restrict__ w2h,
                                unsigned long long* __restrict__ mbits) {
    __shared__ float t[32][33];
    __shared__ int cnt[5];
    const int tid = threadIdx.x;
    const int bz = blockIdx.x;

    if (bz < F2H_BLKS) {
        int i = bz * 256 + tid;
        float4 v = x[i];
        uint2 o;
        o.x = pack_h2(v.x, v.y);
        o.y = pack_h2(v.z, v.w);
        xh[i] = o;
    } else if (bz < F2H_BLKS + TRW_BLKS + TRF_BLKS) {
        int b = bz - F2H_BLKS;
        const float* in; __half* outp; int N, bx, by;
        if (b < TRW_BLKS) { in = wk;  outp = wh;  N = E3; bx = b % 96; by = b / 96; }
        else { b -= TRW_BLKS; in = fck; outp = w2h; N = Ed; bx = b & 31; by = b >> 5; }
        int n0 = bx * 32, k0 = by * 32;
        int tx = tid & 31, ty = tid >> 5;
        for (int i = ty; i < 32; i += 8)
            t[i][tx] = in[(size_t)(k0 + i) * N + n0 + tx];
        __syncthreads();
        for (int i = ty; i < 32; i += 8)
            outp[(size_t)(n0 + i) * Ed + k0 + tx] = __float2half_rn(t[tx][i]);
    } else {
        if (tid < 5) cnt[tid] = 0;
        __syncthreads();
        {
            const unsigned char* m8 = (const unsigned char*)mask;
            int loc[5] = {0, 0, 0, 0, 0};
            for (int i = tid; i < 16384; i += 256) {
                unsigned char v = m8[i];
                if (v) { loc[i & 3]++; if (v != 1) loc[4]++; }
            }
#pragma unroll
            for (int j = 0; j < 5; j++) if (loc[j]) atomicAdd(&cnt[j], loc[j]);
        }
        __syncthreads();
        int mode;
        {
            int c0 = cnt[0], c1 = cnt[1], c2 = cnt[2], c3 = cnt[3], weird = cnt[4];
            if (c1 == 0 && c2 == 0 && c3 == 0) mode = 1;
            else if (c0 == 0 && c1 == 0)       mode = 2;
            else if (weird > 0)                mode = 3;
            else                               mode = 0;
        }
        int w = (bz - (F2H_BLKS + TRW_BLKS + TRF_BLKS)) * 256 + tid;
        unsigned long long bits = 0;
        if (mode == 0) {
            const uint4* p = (const uint4*)((const unsigned char*)mask + (size_t)w * 64);
#pragma unroll
            for (int i = 0; i < 4; i++) {
                uint4 v = p[i];
                uint32_t ws[4] = {v.x, v.y, v.z, v.w};
#pragma unroll
                for (int j = 0; j < 4; j++)
#pragma unroll
                    for (int bq = 0; bq < 4; bq++)
                        if ((ws[j] >> (8 * bq)) & 0xFFu)
                            bits |= 1ull << (i * 16 + j * 4 + bq);
            }
        } else if (mode == 1 || mode == 2) {
            const uint4* p = (const uint4*)((const uint32_t*)mask + (size_t)w * 64);
#pragma unroll
            for (int i = 0; i < 16; i++) {
                uint4 v = p[i];
                if (v.x) bits |= 1ull << (i * 4 + 0);
                if (v.y) bits |= 1ull << (i * 4 + 1);
                if (v.z) bits |= 1ull << (i * 4 + 2);
                if (v.w) bits |= 1ull << (i * 4 + 3);
            }
        } else {
            const uint4* p = (const uint4*)((const unsigned short*)mask + (size_t)w * 64);
#pragma unroll
            for (int i = 0; i < 8; i++) {
                uint4 v = p[i];
                uint32_t ws[4] = {v.x, v.y, v.z, v.w};
#pragma unroll
                for (int j = 0; j < 4; j++) {
                    if (ws[j] & 0xFFFFu) bits |= 1ull << (i * 8 + j * 2);
                    if (ws[j] >> 16)     bits |= 1ull << (i * 8 + j * 2 + 1);
                }
            }
        }
        mbits[w] = bits;
    }
}

// ---------------- fp16 mma.sync GEMM: 128x64 tile, 3 CTAs/SM -----------------
// 8 warps as 4(m) x 2(n); warp tile 32x32 = 2 m-atoms x 4 n-atoms.
// 3-stage cp.async pipeline, 1 sync/iter. ~70 regs -> 24 warps/SM.
#define GLD 40
#define GBK 32
#define ASTG (128 * GLD * 2)             // 10240
#define BSTG (64 * GLD * 2)              // 5120
#define STGB (ASTG + BSTG)               // 15360
#define GEMM_SMEM (3 * STGB)             // 46080

template<int MODE>
__global__ __launch_bounds__(256, 3)
void hgemm_k(const __half* __restrict__ A, const __half* __restrict__ Bt,
             const float* __restrict__ bias, float* __restrict__ C,
             __half* __restrict__ qh2, __half* __restrict__ kh2,
             __half* __restrict__ vh, int N, int K)
{
    extern __shared__ char gsm[];
    const uint32_t sm_base = smem_u32(gsm);

    const int tid = threadIdx.x;
    const int warp = tid >> 5, lane = tid & 31;
    const int gid = lane >> 2, tig = lane & 3;
    const int lr = lane & 7, lq = lane >> 3;
    const int m0 = blockIdx.y * 128, n0 = blockIdx.x * 64;
    const int wm0 = (warp & 3) * 32;
    const int wn0 = (warp >> 2) * 32;

    const __half* Ab = A + (size_t)m0 * K;
    const __half* Bb = Bt + (size_t)n0 * K;

    float acc[2][4][4];
#pragma unroll
    for (int i = 0; i < 2; i++)
#pragma unroll
        for (int j = 0; j < 4; j++)
#pragma unroll
            for (int r = 0; r < 4; r++) acc[i][j][r] = 0.f;

    // loads per stage: A 512 chunks (2/thread), B 256 chunks (1/thread)
    const int lrA0 = tid >> 2,         lcA = (tid & 3) * 8;
    const int lrA1 = (tid + 256) >> 2;
    const int lrB  = tid >> 2;         // 0..63

    const int NS = K / GBK;   // 32

#pragma unroll
    for (int ps = 0; ps < 2; ps++) {
        uint32_t asb = sm_base + ps * STGB;
        uint32_t bsb = asb + ASTG;
        int kb = ps * GBK;
        cp_async16(asb + (lrA0 * GLD + lcA) * 2, Ab + (size_t)lrA0 * K + kb + lcA);
        cp_async16(asb + (lrA1 * GLD + lcA) * 2, Ab + (size_t)lrA1 * K + kb + lcA);
        cp_async16(bsb + (lrB  * GLD + lcA) * 2, Bb + (size_t)lrB  * K + kb + lcA);
        CP_COMMIT();
    }

    const int a_row_off = (lq & 1) * 8 + lr;
    const int a_col_off = (lq >> 1) * 8;
    const int b_row_off = (lq >> 1) * 8 + lr;
    const int b_col_off = (lq & 1) * 8;

    for (int s = 0; s < NS; ++s) {
        if (s == NS - 1) { CP_WAIT(0); } else { CP_WAIT(1); }
        __syncthreads();
        if (s + 2 < NS) {
            int st = (s + 2) % 3;
            int kb = (s + 2) * GBK;
            uint32_t asb = sm_base + st * STGB;
            uint32_t bsb = asb + ASTG;
            cp_async16(asb + (lrA0 * GLD + lcA) * 2, Ab + (size_t)lrA0 * K + kb + lcA);
            cp_async16(asb + (lrA1 * GLD + lcA) * 2, Ab + (size_t)lrA1 * K + kb + lcA);
            cp_async16(bsb + (lrB  * GLD + lcA) * 2, Bb + (size_t)lrB  * K + kb + lcA);
            CP_COMMIT();
        }
        int cs = s % 3;
        uint32_t asb = sm_base + cs * STGB;
        uint32_t bsb = asb + ASTG;
#pragma unroll
        for (int kk = 0; kk < GBK; kk += 16) {
            uint32_t afr[2][4];
#pragma unroll
            for (int i = 0; i < 2; i++) {
                uint32_t addr = asb + ((wm0 + 16 * i + a_row_off) * GLD + kk + a_col_off) * 2;
                LDM_X4(afr[i][0], afr[i][1], afr[i][2], afr[i][3], addr);
            }
            uint32_t bfr[4][2];
#pragma unroll
            for (int jj = 0; jj < 4; jj += 2) {
                uint32_t addr = bsb + ((wn0 + 8 * jj + b_row_off) * GLD + kk + b_col_off) * 2;
                LDM_X4(bfr[jj][0], bfr[jj][1], bfr[jj + 1][0], bfr[jj + 1][1], addr);
            }
#pragma unroll
            for (int j = 0; j < 4; j++) {
                mma_f16(acc[0][j], afr[0], bfr[j][0], bfr[j][1]);
                mma_f16(acc[1][j], afr[1], bfr[j][0], bfr[j][1]);
            }
        }
    }

#pragma unroll
    for (int i = 0; i < 2; i++) {
        int row = m0 + wm0 + 16 * i + gid;
#pragma unroll
        for (int j = 0; j < 4; j++) {
            int col = n0 + wn0 + 8 * j + 2 * tig;
            float2 bv = *(const float2*)&bias[col];
            float v00 = acc[i][j][0] + bv.x, v01 = acc[i][j][1] + bv.y;
            float v10 = acc[i][j][2] + bv.x, v11 = acc[i][j][3] + bv.y;
            if (MODE == 0) {
                float2 o0, o1;
                o0.x = v00; o0.y = v01; o1.x = v10; o1.y = v11;
                *(float2*)&C[(size_t)row * N + col]       = o0;
                *(float2*)&C[(size_t)(row + 8) * N + col] = o1;
            } else {
                int lc = col & 1023;
                if (col < Ed) {
                    *(uint32_t*)&qh2[(size_t)row * Ed + lc] =
                        pack_h2(v00 * QSCALE, v01 * QSCALE);
                    *(uint32_t*)&qh2[(size_t)(row + 8) * Ed + lc] =
                        pack_h2(v10 * QSCALE, v11 * QSCALE);
                } else if (col < 2 * Ed) {
                    *(uint32_t*)&kh2[(size_t)row * Ed + lc]       = pack_h2(v00, v01);
                    *(uint32_t*)&kh2[(size_t)(row + 8) * Ed + lc] = pack_h2(v10, v11);
                } else {
                    *(uint32_t*)&vh[(size_t)row * Ed + lc]       = pack_h2(v00, v01);
                    *(uint32_t*)&vh[(size_t)(row + 8) * Ed + lc] = pack_h2(v10, v11);
                }
            }
        }
    }
}

// ---------------- fp16 flash attention (R11 proven: 3-stage, 1 sync/iter) ----
#define LK 72
#define KH_BYTES (64 * LK * 2)               // 9216
#define QH_BYTES (128 * LK * 2)              // 18432
#define AT_SMEM (QH_BYTES + 6 * KH_BYTES)    // 73728

__global__ __launch_bounds__(256, 2)
void attention_f16_kernel(const __half* __restrict__ qh2,
                          const __half* __restrict__ kh2,
                          const __half* __restrict__ vh,
                          const unsigned long long* __restrict__ mbits,
                          __half* __restrict__ ctxh) {
    extern __shared__ char asmem[];
    const uint32_t qh_smb = smem_u32(asmem);
    const uint32_t kh_smb = qh_smb + QH_BYTES;
    const uint32_t vs_smb = kh_smb + 3 * KH_BYTES;
    const __half* QHs = (const __half*)asmem;

    const int qt = blockIdx.x, bh = blockIdx.y;
    const int b = bh >> 4, h = bh & 15;
    const int tid = threadIdx.x, lane = tid & 31, warp = tid >> 5;
    const int gid = lane >> 2, tig = lane & 3;
    const int lr = lane & 7, lq = lane >> 3;
    const int q0 = qt * 128, hoff = h * Dh;
    const size_t bS = (size_t)b * Sq;
    const int wrow = warp * 16;
    const int r0 = wrow + gid, r1 = r0 + 8;

    const uint32_t k_ldm_off = (lr * LK + 8 * lq) * 2;
    const uint32_t v_ldm_off = (((lq & 1) * 8 + lr) * LK + (lq >> 1) * 8) * 2;

    const int NT = Sq / 64;   // 32

    // prologue: group1 = {Q, K0, V0}; group2 = {K1, V1}
#pragma unroll
    for (int t = 0; t < 4; t++) {
        int idx = tid + t * 256;
        int r = idx >> 3, c = (idx & 7) * 8;
        cp_async16(qh_smb + (r * LK + c) * 2, qh2 + (bS + q0 + r) * Ed + hoff + c);
    }
#pragma unroll
    for (int t = 0; t < 2; t++) {
        int idx = tid + t * 256;
        int r = idx >> 3, c = (idx & 7) * 8;
        cp_async16(kh_smb + (r * LK + c) * 2, kh2 + (bS + r) * Ed + hoff + c);
        cp_async16(vs_smb + (r * LK + c) * 2, vh  + (bS + r) * Ed + hoff + c);
    }
    CP_COMMIT();
#pragma unroll
    for (int t = 0; t < 2; t++) {
        int idx = tid + t * 256;
        int r = idx >> 3, c = (idx & 7) * 8;
        cp_async16(kh_smb + KH_BYTES + (r * LK + c) * 2, kh2 + (bS + 64 + r) * Ed + hoff + c);
        cp_async16(vs_smb + KH_BYTES + (r * LK + c) * 2, vh  + (bS + 64 + r) * Ed + hoff + c);
    }
    CP_COMMIT();

    CP_WAIT(1);
    __syncthreads();

    uint32_t qf[4][4];
#pragma unroll
    for (int kc = 0; kc < 4; kc++) {
        qf[kc][0] = *(const uint32_t*)&QHs[r0 * LK + 16 * kc + 2 * tig];
        qf[kc][1] = *(const uint32_t*)&QHs[r1 * LK + 16 * kc + 2 * tig];
        qf[kc][2] = *(const uint32_t*)&QHs[r0 * LK + 16 * kc + 8 + 2 * tig];
        qf[kc][3] = *(const uint32_t*)&QHs[r1 * LK + 16 * kc + 8 + 2 * tig];
    }

    const unsigned long long* mr0 = mbits + (bS + q0 + r0) * (Sq / 64);
    const unsigned long long* mr1 = mbits + (bS + q0 + r1) * (Sq / 64);

    float oacc[8][4], osum[4];
#pragma unroll
    for (int j = 0; j < 8; j++)
#pragma unroll
        for (int r = 0; r < 4; r++) oacc[j][r] = 0.f;
#pragma unroll
    for (int r = 0; r < 4; r++) osum[r] = 0.f;

    const uint32_t ONES = 0x3C003C00u;

    for (int kt = 0; kt < NT; kt++) {
        if (kt > 0) {
            if (kt == NT - 1) { CP_WAIT(0); } else { CP_WAIT(1); }
            __syncthreads();
        }
        if (kt + 2 < NT) {
            int st = (kt + 2) % 3;
            int k0n = (kt + 2) * 64;
            uint32_t kb = kh_smb + st * KH_BYTES;
            uint32_t vb = vs_smb + st * KH_BYTES;
#pragma unroll
            for (int t = 0; t < 2; t++) {
                int idx = tid + t * 256;
                int r = idx >> 3, c = (idx & 7) * 8;
                cp_async16(kb + (r * LK + c) * 2, kh2 + (bS + k0n + r) * Ed + hoff + c);
                cp_async16(vb + (r * LK + c) * 2, vh  + (bS + k0n + r) * Ed + hoff + c);
            }
            CP_COMMIT();
        }
        const int buf = kt % 3;
        const uint32_t kbase = kh_smb + buf * KH_BYTES + k_ldm_off;
        const uint32_t vbase = vs_smb + buf * KH_BYTES + v_ldm_off;

        unsigned long long mb0 = mr0[kt];
        unsigned long long mb1 = mr1[kt];

        // QK^T via ldmatrix.x4 B-fragments
        float sc[8][4];
#pragma unroll
        for (int j = 0; j < 8; j++)
#pragma unroll
            for (int r = 0; r < 4; r++) sc[j][r] = 0.f;
#pragma unroll
        for (int j = 0; j < 8; j++) {
            uint32_t kaddr = kbase + j * (8 * LK * 2);
            uint32_t k0r, k1r, k2r, k3r, k4r, k5r, k6r, k7r;
            LDM_X4(k0r, k1r, k2r, k3r, kaddr);
            LDM_X4(k4r, k5r, k6r, k7r, kaddr + 64);
            mma_f16(sc[j], qf[0], k0r, k1r);
            mma_f16(sc[j], qf[1], k2r, k3r);
            mma_f16(sc[j], qf[2], k4r, k5r);
            mma_f16(sc[j], qf[3], k6r, k7r);
        }

        // mask quirk + clamp + fp16 pack + 2^y
        uint32_t pp[8][2];
#pragma unroll
        for (int j = 0; j < 8; j++) {
            int col = 8 * j + 2 * tig;
            float y00 = ((mb0 >> col) & 1)       ? MASKC : fminf(sc[j][0], 14.f);
            float y01 = ((mb0 >> (col + 1)) & 1) ? MASKC : fminf(sc[j][1], 14.f);
            float y10 = ((mb1 >> col) & 1)       ? MASKC : fminf(sc[j][2], 14.f);
            float y11 = ((mb1 >> (col + 1)) & 1) ? MASKC : fminf(sc[j][3], 14.f);
            pp[j][0] = ex2_h2(pack_h2(y00, y01));
            pp[j][1] = ex2_h2(pack_h2(y10, y11));
        }

        // PV (+ ones-column denominator) via ldmatrix.x4.trans V fragments
#pragma unroll
        for (int kc = 0; kc < 4; kc++) {
            uint32_t a[4] = { pp[2 * kc][0], pp[2 * kc][1],
                              pp[2 * kc + 1][0], pp[2 * kc + 1][1] };
            mma_f16(osum, a, ONES, ONES);
#pragma unroll
            for (int jj = 0; jj < 8; jj += 2) {
                uint32_t b0, b1, b2, b3;
                LDM_X4_T(b0, b1, b2, b3,
                         vbase + (16 * kc * LK + 8 * jj) * 2);
                mma_f16(oacc[jj],     a, b0, b1);
                mma_f16(oacc[jj + 1], a, b2, b3);
            }
        }
    }

    float inv0 = 1.f / osum[0], inv1 = 1.f / osum[2];
    const size_t row0 = bS + q0 + wrow + gid;
#pragma unroll
    for (int j = 0; j < 8; j++) {
        int col = hoff + 8 * j + 2 * tig;
        *(uint32_t*)&ctxh[row0 * Ed + col] =
            pack_h2(oacc[j][0] * inv0, oacc[j][1] * inv0);
        *(uint32_t*)&ctxh[(row0 + 8) * Ed + col] =
            pack_h2(oacc[j][2] * inv1, oacc[j][3] * inv1);
    }
}

// ---------------- launcher ----------------
extern "C" void kernel_launch(void* const* d_in, const int* in_sizes, int n_in,
                              void* d_out, int out_size) {
    const float* x        = (const float*)d_in[0];
    const void*  amask    = d_in[1];
    const float* w_kernel = (const float*)d_in[2];
    const float* w_bias   = (const float*)d_in[3];
    const float* fc_kernel= (const float*)d_in[4];
    const float* fc_bias  = (const float*)d_in[5];
    float* out = (float*)d_out;

    __half *xh, *wh, *w2h, *qh2, *kh2, *vh, *ctxh;
    unsigned long long* mbits;
    cudaGetSymbolAddress((void**)&xh,   g_xh);
    cudaGetSymbolAddress((void**)&wh,   g_wh);
    cudaGetSymbolAddress((void**)&w2h,  g_w2h);
    cudaGetSymbolAddress((void**)&qh2,  g_qh2);
    cudaGetSymbolAddress((void**)&kh2,  g_kh2);
    cudaGetSymbolAddress((void**)&vh,   g_vh);
    cudaGetSymbolAddress((void**)&ctxh, g_ctxh);
    cudaGetSymbolAddress((void**)&mbits, g_mbits);

    cudaFuncSetAttribute(hgemm_k<1>, cudaFuncAttributeMaxDynamicSharedMemorySize, GEMM_SMEM);
    cudaFuncSetAttribute(hgemm_k<0>, cudaFuncAttributeMaxDynamicSharedMemorySize, GEMM_SMEM);
    cudaFuncSetAttribute(attention_f16_kernel,
                         cudaFuncAttributeMaxDynamicSharedMemorySize, AT_SMEM);

    // 1. fused prep
    prep_all_kernel<<<PREP_BLKS, 256>>>((const float4*)x, w_kernel, fc_kernel,
                                        amask, (uint2*)xh, wh, w2h, mbits);

    // 2. QKV projection with fused fp16 split epilogue (128x64 tiles)
    hgemm_k<1><<<dim3(E3 / 64, Mrows / 128), 256, GEMM_SMEM>>>(
        xh, wh, w_bias, nullptr, qh2, kh2, vh, E3, Ed);

    // 3. fp16 flash attention
    {
        dim3 grid(Sq / 128, Bz * Hh);
        attention_f16_kernel<<<grid, 256, AT_SMEM>>>(qh2, kh2, vh, mbits, ctxh);
    }

    // 4. output projection (128x64 tiles)
    hgemm_k<0><<<dim3(Ed / 64, Mrows / 128), 256, GEMM_SMEM>>>(
        ctxh, w2h, fc_bias, out, nullptr, nullptr, nullptr, Ed, Ed);
}

// round 14
// speedup vs baseline: 1.0896x; 1.0896x over previous
#include <cuda_runtime.h>
#include <cuda_fp16.h>
#include <cstdint>
#include <math.h>

// Problem constants
#define Bz 2
#define Sq 2048
#define Ed 1024
#define Hh 16
#define Dh 64
#define E3 3072
#define Mrows (Bz*Sq)   // 4096

// score domain: y = (q.k) * 0.125 * log2(e); folded into Q at GEMM epilogue
#define QSCALE 0.18033688011112042f
#define MASKC  1.4426950408889634e-9f   // 1e-9 * log2(e)

// ---------------- device scratch ----------------
__device__ __align__(16) __half g_xh [Bz * Sq * Ed];
__device__ __align__(16) __half g_wh [E3 * Ed];
__device__ __align__(16) __half g_w2h[Ed * Ed];
__device__ __align__(16) __half g_qh2[Bz * Sq * Ed];
__device__ __align__(16) __half g_kh2[Bz * Sq * Ed];
__device__ __align__(16) __half g_vh [Bz * Sq * Ed];
__device__ __align__(16) __half g_ctxh[Bz * Sq * Ed];
__device__ __align__(16) unsigned long long g_mbits[(size_t)Bz * Sq * Sq / 64];

// ---------------- base-PTX helpers ----------------
__device__ __forceinline__ uint32_t smem_u32(const void* p) {
    uint32_t a;
    asm("{ .reg .u64 t; cvta.to.shared.u64 t, %1; cvt.u32.u64 %0, t; }" : "=r"(a) : "l"(p));
    return a;
}
__device__ __forceinline__ void cp_async16(uint32_t dst, const void* src) {
    asm volatile("cp.async.cg.shared.global [%0], [%1], 16;" :: "r"(dst), "l"(src));
}
#define CP_COMMIT() asm volatile("cp.async.commit_group;" ::: "memory")
#define CP_WAIT(n)  asm volatile("cp.async.wait_group %0;" :: "n"(n) : "memory")

__device__ __forceinline__ void mma_f16(float* d, const uint32_t* a, uint32_t b0, uint32_t b1) {
    asm volatile("mma.sync.aligned.m16n8k16.row.col.f32.f16.f16.f32 "
                 "{%0,%1,%2,%3}, {%4,%5,%6,%7}, {%8,%9}, {%0,%1,%2,%3};"
                 : "+f"(d[0]), "+f"(d[1]), "+f"(d[2]), "+f"(d[3])
                 : "r"(a[0]), "r"(a[1]), "r"(a[2]), "r"(a[3]), "r"(b0), "r"(b1));
}
__device__ __forceinline__ uint32_t pack_h2(float lo, float hi) {
    uint32_t r; asm("cvt.rn.f16x2.f32 %0, %1, %2;" : "=r"(r) : "f"(hi), "f"(lo)); return r;
}
__device__ __forceinline__ uint32_t ex2_h2(uint32_t y) {
    uint32_t r; asm("ex2.approx.f16x2 %0, %1;" : "=r"(r) : "r"(y)); return r;
}
#define LDM_X4(r0, r1, r2, r3, addr) \
    asm volatile("ldmatrix.sync.aligned.m8n8.x4.shared.b16 {%0,%1,%2,%3}, [%4];" \
                 : "=r"(r0), "=r"(r1), "=r"(r2), "=r"(r3) : "r"(addr))
#define LDM_X4_T(r0, r1, r2, r3, addr) \
    asm volatile("ldmatrix.sync.aligned.m8n8.x4.trans.shared.b16 {%0,%1,%2,%3}, [%4];" \
                 : "=r"(r0), "=r"(r1), "=r"(r2), "=r"(r3) : "r"(addr))

// ---------------- prep kernel A: x->fp16 + w^T (hgemm1 dependencies) --------
#define F2H_BLKS 4096
#define TRW_BLKS 3072
#define PXW_BLKS (F2H_BLKS + TRW_BLKS)

__global__ void prep_xw_kernel(const float4* __restrict__ x,
                               const float* __restrict__ wk,
                               uint2* __restrict__ xh,
                               __half* __restrict__ wh) {
    __shared__ float t[32][33];
    const int tid = threadIdx.x;
    const int bz = blockIdx.x;
    if (bz < F2H_BLKS) {
        int i = bz * 256 + tid;
        float4 v = x[i];
        uint2 o;
        o.x = pack_h2(v.x, v.y);
        o.y = pack_h2(v.z, v.w);
        xh[i] = o;
    } else {
        int b = bz - F2H_BLKS;
        int bx = b % 96, by = b / 96;
        int n0 = bx * 32, k0 = by * 32;
        int tx = tid & 31, ty = tid >> 5;
        for (int i = ty; i < 32; i += 8)
            t[i][tx] = wk[(size_t)(k0 + i) * E3 + n0 + tx];
        __syncthreads();
        for (int i = ty; i < 32; i += 8)
            wh[(size_t)(n0 + i) * Ed + k0 + tx] = __float2half_rn(t[tx][i]);
    }
}

// ---------------- prep kernel B: fc^T + mask pack (independent; overlaps) ---
#define TRF_BLKS 1024
#define PACK_BLKS 512
#define PFM_BLKS (TRF_BLKS + PACK_BLKS)

__global__ void prep_fcmask_kernel(const float* __restrict__ fck,
                                   const void* __restrict__ mask,
                                   __half* __restrict__ w2h,
                                   unsigned long long* __restrict__ mbits) {
    __shared__ float t[32][33];
    __shared__ int cnt[5];
    const int tid = threadIdx.x;
    const int bz = blockIdx.x;
    if (bz < TRF_BLKS) {
        int bx = bz & 31, by = bz >> 5;
        int n0 = bx * 32, k0 = by * 32;
        int tx = tid & 31, ty = tid >> 5;
        for (int i = ty; i < 32; i += 8)
            t[i][tx] = fck[(size_t)(k0 + i) * Ed + n0 + tx];
        __syncthreads();
        for (int i = ty; i < 32; i += 8)
            w2h[(size_t)(n0 + i) * Ed + k0 + tx] = __float2half_rn(t[tx][i]);
    } else {
        // ---- mask bit-pack with inline dtype detection (proven R10) ----
        if (tid < 5) cnt[tid] = 0;
        __syncthreads();
        {
            const unsigned char* m8 = (const unsigned char*)mask;
            int loc[5] = {0, 0, 0, 0, 0};
            for (int i = tid; i < 16384; i += 256) {
                unsigned char v = m8[i];
                if (v) { loc[i & 3]++; if (v != 1) loc[4]++; }
            }
#pragma unroll
            for (int j = 0; j < 5; j++) if (loc[j]) atomicAdd(&cnt[j], loc[j]);
        }
        __syncthreads();
        int mode;
        {
            int c0 = cnt[0], c1 = cnt[1], c2 = cnt[2], c3 = cnt[3], weird = cnt[4];
            if (c1 == 0 && c2 == 0 && c3 == 0) mode = 1;
            else if (c0 == 0 && c1 == 0)       mode = 2;
            else if (weird > 0)                mode = 3;
            else                               mode = 0;
        }
        int w = (bz - TRF_BLKS) * 256 + tid;
        unsigned long long bits = 0;
        if (mode == 0) {
            const uint4* p = (const uint4*)((const unsigned char*)mask + (size_t)w * 64);
#pragma unroll
            for (int i = 0; i < 4; i++) {
                uint4 v = p[i];
                uint32_t ws[4] = {v.x, v.y, v.z, v.w};
#pragma unroll
                for (int j = 0; j < 4; j++)
#pragma unroll
                    for (int bq = 0; bq < 4; bq++)
                        if ((ws[j] >> (8 * bq)) & 0xFFu)
                            bits |= 1ull << (i * 16 + j * 4 + bq);
            }
        } else if (mode == 1 || mode == 2) {
            const uint4* p = (const uint4*)((const uint32_t*)mask + (size_t)w * 64);
#pragma unroll
            for (int i = 0; i < 16; i++) {
                uint4 v = p[i];
                if (v.x) bits |= 1ull << (i * 4 + 0);
                if (v.y) bits |= 1ull << (i * 4 + 1);
                if (v.z) bits |= 1ull << (i * 4 + 2);
                if (v.w) bits |= 1ull << (i * 4 + 3);
            }
        } else {
            const uint4* p = (const uint4*)((const unsigned short*)mask + (size_t)w * 64);
#pragma unroll
            for (int i = 0; i < 8; i++) {
                uint4 v = p[i];
                uint32_t ws[4] = {v.x, v.y, v.z, v.w};
#pragma unroll
                for (int j = 0; j < 4; j++) {
                    if (ws[j] & 0xFFFFu) bits |= 1ull << (i * 8 + j * 2);
                    if (ws[j] >> 16)     bits |= 1ull << (i * 8 + j * 2 + 1);
                }
            }
        }
        mbits[w] = bits;
    }
}

// ---------------- fp16 mma.sync GEMM: 128x128, 3-stage, 1 sync (R11 best) ---
#define GLD 40
#define GBK 32
#define GSTGB (128 * GLD * 2)            // 10240
#define GEMM_SMEM (6 * GSTGB)            // 61440

template<int MODE>
__global__ __launch_bounds__(256, 2)
void hgemm_k(const __half* __restrict__ A, const __half* __restrict__ Bt,
             const float* __restrict__ bias, float* __restrict__ C,
             __half* __restrict__ qh2, __half* __restrict__ kh2,
             __half* __restrict__ vh, int N, int K)
{
    extern __shared__ char gsm[];
    const uint32_t as_base = smem_u32(gsm);
    const uint32_t bs_base = as_base + 3 * GSTGB;

    const int tid = threadIdx.x;
    const int warp = tid >> 5, lane = tid & 31;
    const int gid = lane >> 2, tig = lane & 3;
    const int lr = lane & 7, lq = lane >> 3;
    const int m0 = blockIdx.y * 128, n0 = blockIdx.x * 128;
    const int wm0 = (warp & 3) * 32;
    const int wn0 = (warp >> 2) * 64;

    const __half* Ab = A + (size_t)m0 * K;
    const __half* Bb = Bt + (size_t)n0 * K;

    float acc[2][8][4];
#pragma unroll
    for (int i = 0; i < 2; i++)
#pragma unroll
        for (int j = 0; j < 8; j++)
#pragma unroll
            for (int r = 0; r < 4; r++) acc[i][j][r] = 0.f;

    const int lr0 = tid >> 2,          lc0 = (tid & 3) * 8;
    const int lr1 = (tid + 256) >> 2,  lc1 = (tid & 3) * 8;

    const int NS = K / GBK;   // 32

#pragma unroll
    for (int ps = 0; ps < 2; ps++) {
        uint32_t asb = as_base + ps * GSTGB;
        uint32_t bsb = bs_base + ps * GSTGB;
        int kb = ps * GBK;
        cp_async16(asb + (lr0 * GLD + lc0) * 2, Ab + (size_t)lr0 * K + kb + lc0);
        cp_async16(asb + (lr1 * GLD + lc1) * 2, Ab + (size_t)lr1 * K + kb + lc1);
        cp_async16(bsb + (lr0 * GLD + lc0) * 2, Bb + (size_t)lr0 * K + kb + lc0);
        cp_async16(bsb + (lr1 * GLD + lc1) * 2, Bb + (size_t)lr1 * K + kb + lc1);
        CP_COMMIT();
    }

    const int a_row_off = (lq & 1) * 8 + lr;
    const int a_col_off = (lq >> 1) * 8;
    const int b_row_off = (lq >> 1) * 8 + lr;
    const int b_col_off = (lq & 1) * 8;

    for (int s = 0; s < NS; ++s) {
        if (s == NS - 1) { CP_WAIT(0); } else { CP_WAIT(1); }
        __syncthreads();
        if (s + 2 < NS) {
            int st = (s + 2) % 3;
            int kb = (s + 2) * GBK;
            uint32_t asb = as_base + st * GSTGB;
            uint32_t bsb = bs_base + st * GSTGB;
            cp_async16(asb + (lr0 * GLD + lc0) * 2, Ab + (size_t)lr0 * K + kb + lc0);
            cp_async16(asb + (lr1 * GLD + lc1) * 2, Ab + (size_t)lr1 * K + kb + lc1);
            cp_async16(bsb + (lr0 * GLD + lc0) * 2, Bb + (size_t)lr0 * K + kb + lc0);
            cp_async16(bsb + (lr1 * GLD + lc1) * 2, Bb + (size_t)lr1 * K + kb + lc1);
            CP_COMMIT();
        }
        int cs = s % 3;
        uint32_t asb = as_base + cs * GSTGB;
        uint32_t bsb = bs_base + cs * GSTGB;
#pragma unroll
        for (int kk = 0; kk < GBK; kk += 16) {
            uint32_t afr[2][4];
#pragma unroll
            for (int i = 0; i < 2; i++) {
                uint32_t addr = asb + ((wm0 + 16 * i + a_row_off) * GLD + kk + a_col_off) * 2;
                LDM_X4(afr[i][0], afr[i][1], afr[i][2], afr[i][3], addr);
            }
            uint32_t bfr[8][2];
#pragma unroll
            for (int jj = 0; jj < 8; jj += 2) {
                uint32_t addr = bsb + ((wn0 + 8 * jj + b_row_off) * GLD + kk + b_col_off) * 2;
                LDM_X4(bfr[jj][0], bfr[jj][1], bfr[jj + 1][0], bfr[jj + 1][1], addr);
            }
#pragma unroll
            for (int j = 0; j < 8; j++) {
                mma_f16(acc[0][j], afr[0], bfr[j][0], bfr[j][1]);
                mma_f16(acc[1][j], afr[1], bfr[j][0], bfr[j][1]);
            }
        }
    }

#pragma unroll
    for (int i = 0; i < 2; i++) {
        int row = m0 + wm0 + 16 * i + gid;
#pragma unroll
        for (int j = 0; j < 8; j++) {
            int col = n0 + wn0 + 8 * j + 2 * tig;
            float2 bv = *(const float2*)&bias[col];
            float v00 = acc[i][j][0] + bv.x, v01 = acc[i][j][1] + bv.y;
            float v10 = acc[i][j][2] + bv.x, v11 = acc[i][j][3] + bv.y;
            if (MODE == 0) {
                float2 o0, o1;
                o0.x = v00; o0.y = v01; o1.x = v10; o1.y = v11;
                *(float2*)&C[(size_t)row * N + col]       = o0;
                *(float2*)&C[(size_t)(row + 8) * N + col] = o1;
            } else {
                int lc = col & 1023;
                if (col < Ed) {
                    *(uint32_t*)&qh2[(size_t)row * Ed + lc] =
                        pack_h2(v00 * QSCALE, v01 * QSCALE);
                    *(uint32_t*)&qh2[(size_t)(row + 8) * Ed + lc] =
                        pack_h2(v10 * QSCALE, v11 * QSCALE);
                } else if (col < 2 * Ed) {
                    *(uint32_t*)&kh2[(size_t)row * Ed + lc]       = pack_h2(v00, v01);
                    *(uint32_t*)&kh2[(size_t)(row + 8) * Ed + lc] = pack_h2(v10, v11);
                } else {
                    *(uint32_t*)&vh[(size_t)row * Ed + lc]       = pack_h2(v00, v01);
                    *(uint32_t*)&vh[(size_t)(row + 8) * Ed + lc] = pack_h2(v10, v11);
                }
            }
        }
    }
}

// ---------------- fp16 flash attention (R11 proven: 3-stage, 1 sync/iter) ----
#define LK 72
#define KH_BYTES (64 * LK * 2)               // 9216
#define QH_BYTES (128 * LK * 2)              // 18432
#define AT_SMEM (QH_BYTES + 6 * KH_BYTES)    // 73728

__global__ __launch_bounds__(256, 2)
void attention_f16_kernel(const __half* __restrict__ qh2,
                          const __half* __restrict__ kh2,
                          const __half* __restrict__ vh,
                          const unsigned long long* __restrict__ mbits,
                          __half* __restrict__ ctxh) {
    extern __shared__ char asmem[];
    const uint32_t qh_smb = smem_u32(asmem);
    const uint32_t kh_smb = qh_smb + QH_BYTES;
    const uint32_t vs_smb = kh_smb + 3 * KH_BYTES;
    const __half* QHs = (const __half*)asmem;

    const int qt = blockIdx.x, bh = blockIdx.y;
    const int b = bh >> 4, h = bh & 15;
    const int tid = threadIdx.x, lane = tid & 31, warp = tid >> 5;
    const int gid = lane >> 2, tig = lane & 3;
    const int lr = lane & 7, lq = lane >> 3;
    const int q0 = qt * 128, hoff = h * Dh;
    const size_t bS = (size_t)b * Sq;
    const int wrow = warp * 16;
    const int r0 = wrow + gid, r1 = r0 + 8;

    const uint32_t k_ldm_off = (lr * LK + 8 * lq) * 2;
    const uint32_t v_ldm_off = (((lq & 1) * 8 + lr) * LK + (lq >> 1) * 8) * 2;

    const int NT = Sq / 64;   // 32

    // prologue: group1 = {Q, K0, V0}; group2 = {K1, V1}
#pragma unroll
    for (int t = 0; t < 4; t++) {
        int idx = tid + t * 256;
        int r = idx >> 3, c = (idx & 7) * 8;
        cp_async16(qh_smb + (r * LK + c) * 2, qh2 + (bS + q0 + r) * Ed + hoff + c);
    }
#pragma unroll
    for (int t = 0; t < 2; t++) {
        int idx = tid + t * 256;
        int r = idx >> 3, c = (idx & 7) * 8;
        cp_async16(kh_smb + (r * LK + c) * 2, kh2 + (bS + r) * Ed + hoff + c);
        cp_async16(vs_smb + (r * LK + c) * 2, vh  + (bS + r) * Ed + hoff + c);
    }
    CP_COMMIT();
#pragma unroll
    for (int t = 0; t < 2; t++) {
        int idx = tid + t * 256;
        int r = idx >> 3, c = (idx & 7) * 8;
        cp_async16(kh_smb + KH_BYTES + (r * LK + c) * 2, kh2 + (bS + 64 + r) * Ed + hoff + c);
        cp_async16(vs_smb + KH_BYTES + (r * LK + c) * 2, vh  + (bS + 64 + r) * Ed + hoff + c);
    }
    CP_COMMIT();

    CP_WAIT(1);
    __syncthreads();

    uint32_t qf[4][4];
#pragma unroll
    for (int kc = 0; kc < 4; kc++) {
        qf[kc][0] = *(const uint32_t*)&QHs[r0 * LK + 16 * kc + 2 * tig];
        qf[kc][1] = *(const uint32_t*)&QHs[r1 * LK + 16 * kc + 2 * tig];
        qf[kc][2] = *(const uint32_t*)&QHs[r0 * LK + 16 * kc + 8 + 2 * tig];
        qf[kc][3] = *(const uint32_t*)&QHs[r1 * LK + 16 * kc + 8 + 2 * tig];
    }

    const unsigned long long* mr0 = mbits + (bS + q0 + r0) * (Sq / 64);
    const unsigned long long* mr1 = mbits + (bS + q0 + r1) * (Sq / 64);

    float oacc[8][4], osum[4];
#pragma unroll
    for (int j = 0; j < 8; j++)
#pragma unroll
        for (int r = 0; r < 4; r++) oacc[j][r] = 0.f;
#pragma unroll
    for (int r = 0; r < 4; r++) osum[r] = 0.f;

    const uint32_t ONES = 0x3C003C00u;

    for (int kt = 0; kt < NT; kt++) {
        if (kt > 0) {
            if (kt == NT - 1) { CP_WAIT(0); } else { CP_WAIT(1); }
            __syncthreads();
        }
        if (kt + 2 < NT) {
            int st = (kt + 2) % 3;
            int k0n = (kt + 2) * 64;
            uint32_t kb = kh_smb + st * KH_BYTES;
            uint32_t vb = vs_smb + st * KH_BYTES;
#pragma unroll
            for (int t = 0; t < 2; t++) {
                int idx = tid + t * 256;
                int r = idx >> 3, c = (idx & 7) * 8;
                cp_async16(kb + (r * LK + c) * 2, kh2 + (bS + k0n + r) * Ed + hoff + c);
                cp_async16(vb + (r * LK + c) * 2, vh  + (bS + k0n + r) * Ed + hoff + c);
            }
            CP_COMMIT();
        }
        const int buf = kt % 3;
        const uint32_t kbase = kh_smb + buf * KH_BYTES + k_ldm_off;
        const uint32_t vbase = vs_smb + buf * KH_BYTES + v_ldm_off;

        unsigned long long mb0 = mr0[kt];
        unsigned long long mb1 = mr1[kt];

        float sc[8][4];
#pragma unroll
        for (int j = 0; j < 8; j++)
#pragma unroll
            for (int r = 0; r < 4; r++) sc[j][r] = 0.f;
#pragma unroll
        for (int j = 0; j < 8; j++) {
            uint32_t kaddr = kbase + j * (8 * LK * 2);
            uint32_t k0r, k1r, k2r, k3r, k4r, k5r, k6r, k7r;
            LDM_X4(k0r, k1r, k2r, k3r, kaddr);
            LDM_X4(k4r, k5r, k6r, k7r, kaddr + 64);
            mma_f16(sc[j], qf[0], k0r, k1r);
            mma_f16(sc[j], qf[1], k2r, k3r);
            mma_f16(sc[j], qf[2], k4r, k5r);
            mma_f16(sc[j], qf[3], k6r, k7r);
        }

        uint32_t pp[8][2];
#pragma unroll
        for (int j = 0; j < 8; j++) {
            int col = 8 * j + 2 * tig;
            float y00 = ((mb0 >> col) & 1)       ? MASKC : fminf(sc[j][0], 14.f);
            float y01 = ((mb0 >> (col + 1)) & 1) ? MASKC : fminf(sc[j][1], 14.f);
            float y10 = ((mb1 >> col) & 1)       ? MASKC : fminf(sc[j][2], 14.f);
            float y11 = ((mb1 >> (col + 1)) & 1) ? MASKC : fminf(sc[j][3], 14.f);
            pp[j][0] = ex2_h2(pack_h2(y00, y01));
            pp[j][1] = ex2_h2(pack_h2(y10, y11));
        }

#pragma unroll
        for (int kc = 0; kc < 4; kc++) {
            uint32_t a[4] = { pp[2 * kc][0], pp[2 * kc][1],
                              pp[2 * kc + 1][0], pp[2 * kc + 1][1] };
            mma_f16(osum, a, ONES, ONES);
#pragma unroll
            for (int jj = 0; jj < 8; jj += 2) {
                uint32_t b0, b1, b2, b3;
                LDM_X4_T(b0, b1, b2, b3,
                         vbase + (16 * kc * LK + 8 * jj) * 2);
                mma_f16(oacc[jj],     a, b0, b1);
                mma_f16(oacc[jj + 1], a, b2, b3);
            }
        }
    }

    float inv0 = 1.f / osum[0], inv1 = 1.f / osum[2];
    const size_t row0 = bS + q0 + wrow + gid;
#pragma unroll
    for (int j = 0; j < 8; j++) {
        int col = hoff + 8 * j + 2 * tig;
        *(uint32_t*)&ctxh[row0 * Ed + col] =
            pack_h2(oacc[j][0] * inv0, oacc[j][1] * inv0);
        *(uint32_t*)&ctxh[(row0 + 8) * Ed + col] =
            pack_h2(oacc[j][2] * inv1, oacc[j][3] * inv1);
    }
}

// ---------------- launcher with two-stream capture fork ----------------
extern "C" void kernel_launch(void* const* d_in, const int* in_sizes, int n_in,
                              void* d_out, int out_size) {
    const float* x        = (const float*)d_in[0];
    const void*  amask    = d_in[1];
    const float* w_kernel = (const float*)d_in[2];
    const float* w_bias   = (const float*)d_in[3];
    const float* fc_kernel= (const float*)d_in[4];
    const float* fc_bias  = (const float*)d_in[5];
    float* out = (float*)d_out;

    __half *xh, *wh, *w2h, *qh2, *kh2, *vh, *ctxh;
    unsigned long long* mbits;
    cudaGetSymbolAddress((void**)&xh,   g_xh);
    cudaGetSymbolAddress((void**)&wh,   g_wh);
    cudaGetSymbolAddress((void**)&w2h,  g_w2h);
    cudaGetSymbolAddress((void**)&qh2,  g_qh2);
    cudaGetSymbolAddress((void**)&kh2,  g_kh2);
    cudaGetSymbolAddress((void**)&vh,   g_vh);
    cudaGetSymbolAddress((void**)&ctxh, g_ctxh);
    cudaGetSymbolAddress((void**)&mbits, g_mbits);

    // one-time stream/event setup (first call happens BEFORE graph capture)
    static cudaStream_t s2 = nullptr;
    static cudaEvent_t evFork = nullptr, evJoin = nullptr;
    if (s2 == nullptr) {
        cudaStreamCreateWithFlags(&s2, cudaStreamNonBlocking);
        cudaEventCreateWithFlags(&evFork, cudaEventDisableTiming);
        cudaEventCreateWithFlags(&evJoin, cudaEventDisableTiming);
        cudaFuncSetAttribute(hgemm_k<1>, cudaFuncAttributeMaxDynamicSharedMemorySize, GEMM_SMEM);
        cudaFuncSetAttribute(hgemm_k<0>, cudaFuncAttributeMaxDynamicSharedMemorySize, GEMM_SMEM);
        cudaFuncSetAttribute(attention_f16_kernel,
                             cudaFuncAttributeMaxDynamicSharedMemorySize, AT_SMEM);
    }

    // fork: fc-transpose + mask-pack run on s2, overlapped with prep_xw+hgemm1
    cudaEventRecord(evFork, 0);
    cudaStreamWaitEvent(s2, evFork, 0);
    prep_fcmask_kernel<<<PFM_BLKS, 256, 0, s2>>>(fc_kernel, amask, w2h, mbits);
    cudaEventRecord(evJoin, s2);

    // main chain on the legacy stream
    prep_xw_kernel<<<PXW_BLKS, 256>>>((const float4*)x, w_kernel, (uint2*)xh, wh);

    hgemm_k<1><<<dim3(E3 / 128, Mrows / 128), 256, GEMM_SMEM>>>(
        xh, wh, w_bias, nullptr, qh2, kh2, vh, E3, Ed);

    // join: attention needs mbits (s2), hgemm2 needs w2h (s2)
    cudaStreamWaitEvent(0, evJoin, 0);

    {
        dim3 grid(Sq / 128, Bz * Hh);
        attention_f16_kernel<<<grid, 256, AT_SMEM>>>(qh2, kh2, vh, mbits, ctxh);
    }

    hgemm_k<0><<<dim3(Ed / 128, Mrows / 128), 256, GEMM_SMEM>>>(
        ctxh, w2h, fc_bias, out, nullptr, nullptr, nullptr, Ed, Ed);
}

// round 15
// speedup vs baseline: 1.1231x; 1.0307x over previous
#include <cuda_runtime.h>
#include <cuda_fp16.h>
#include <cstdint>
#include <math.h>

// Problem constants
#define Bz 2
#define Sq 2048
#define Ed 1024
#define Hh 16
#define Dh 64
#define E3 3072
#define Mrows (Bz*Sq)   // 4096

// score domain: y = (q.k) * 0.125 * log2(e); folded into Q at GEMM epilogue
#define QSCALE 0.18033688011112042f
#define MASKC  1.4426950408889634e-9f   // 1e-9 * log2(e)

// ---------------- device scratch ----------------
__device__ __align__(16) __half g_xh [Bz * Sq * Ed];
__device__ __align__(16) __half g_wh [E3 * Ed];
__device__ __align__(16) __half g_w2h[Ed * Ed];
__device__ __align__(16) __half g_qh2[Bz * Sq * Ed];
__device__ __align__(16) __half g_kh2[Bz * Sq * Ed];
__device__ __align__(16) __half g_vh [Bz * Sq * Ed];
__device__ __align__(16) __half g_ctxh[Bz * Sq * Ed];
__device__ __align__(16) unsigned long long g_mbits[(size_t)Bz * Sq * Sq / 64];

// ---------------- base-PTX helpers ----------------
__device__ __forceinline__ uint32_t smem_u32(const void* p) {
    uint32_t a;
    asm("{ .reg .u64 t; cvta.to.shared.u64 t, %1; cvt.u32.u64 %0, t; }" : "=r"(a) : "l"(p));
    return a;
}
__device__ __forceinline__ void cp_async16(uint32_t dst, const void* src) {
    asm volatile("cp.async.cg.shared.global [%0], [%1], 16;" :: "r"(dst), "l"(src));
}
#define CP_COMMIT() asm volatile("cp.async.commit_group;" ::: "memory")
#define CP_WAIT(n)  asm volatile("cp.async.wait_group %0;" :: "n"(n) : "memory")

__device__ __forceinline__ void mma_f16(float* d, const uint32_t* a, uint32_t b0, uint32_t b1) {
    asm volatile("mma.sync.aligned.m16n8k16.row.col.f32.f16.f16.f32 "
                 "{%0,%1,%2,%3}, {%4,%5,%6,%7}, {%8,%9}, {%0,%1,%2,%3};"
                 : "+f"(d[0]), "+f"(d[1]), "+f"(d[2]), "+f"(d[3])
                 : "r"(a[0]), "r"(a[1]), "r"(a[2]), "r"(a[3]), "r"(b0), "r"(b1));
}
__device__ __forceinline__ uint32_t pack_h2(float lo, float hi) {
    uint32_t r; asm("cvt.rn.f16x2.f32 %0, %1, %2;" : "=r"(r) : "f"(hi), "f"(lo)); return r;
}
__device__ __forceinline__ uint32_t ex2_h2(uint32_t y) {
    uint32_t r; asm("ex2.approx.f16x2 %0, %1;" : "=r"(r) : "r"(y)); return r;
}
#define LDM_X4(r0, r1, r2, r3, addr) \
    asm volatile("ldmatrix.sync.aligned.m8n8.x4.shared.b16 {%0,%1,%2,%3}, [%4];" \
                 : "=r"(r0), "=r"(r1), "=r"(r2), "=r"(r3) : "r"(addr))
#define LDM_X4_T(r0, r1, r2, r3, addr) \
    asm volatile("ldmatrix.sync.aligned.m8n8.x4.trans.shared.b16 {%0,%1,%2,%3}, [%4];" \
                 : "=r"(r0), "=r"(r1), "=r"(r2), "=r"(r3) : "r"(addr))

// ---------------- prep kernel A: x->fp16 + w^T (hgemm1 dependencies) --------
#define F2H_BLKS 4096
#define TRW_BLKS 3072
#define PXW_BLKS (F2H_BLKS + TRW_BLKS)

__global__ void prep_xw_kernel(const float4* __restrict__ x,
                               const float* __restrict__ wk,
                               uint2* __restrict__ xh,
                               __half* __restrict__ wh) {
    __shared__ float t[32][33];
    const int tid = threadIdx.x;
    const int bz = blockIdx.x;
    if (bz < F2H_BLKS) {
        int i = bz * 256 + tid;
        float4 v = x[i];
        uint2 o;
        o.x = pack_h2(v.x, v.y);
        o.y = pack_h2(v.z, v.w);
        xh[i] = o;
    } else {
        int b = bz - F2H_BLKS;
        int bx = b % 96, by = b / 96;
        int n0 = bx * 32, k0 = by * 32;
        int tx = tid & 31, ty = tid >> 5;
        for (int i = ty; i < 32; i += 8)
            t[i][tx] = wk[(size_t)(k0 + i) * E3 + n0 + tx];
        __syncthreads();
        for (int i = ty; i < 32; i += 8)
            wh[(size_t)(n0 + i) * Ed + k0 + tx] = __float2half_rn(t[tx][i]);
    }
}

// ---------------- prep kernel B: fc^T + mask pack (overlapped stream) -------
#define TRF_BLKS 1024
#define PACK_BLKS 512
#define PFM_BLKS (TRF_BLKS + PACK_BLKS)

__global__ void prep_fcmask_kernel(const float* __restrict__ fck,
                                   const void* __restrict__ mask,
                                   __half* __restrict__ w2h,
                                   unsigned long long* __restrict__ mbits) {
    __shared__ float t[32][33];
    __shared__ int cnt[5];
    const int tid = threadIdx.x;
    const int bz = blockIdx.x;
    if (bz < TRF_BLKS) {
        int bx = bz & 31, by = bz >> 5;
        int n0 = bx * 32, k0 = by * 32;
        int tx = tid & 31, ty = tid >> 5;
        for (int i = ty; i < 32; i += 8)
            t[i][tx] = fck[(size_t)(k0 + i) * Ed + n0 + tx];
        __syncthreads();
        for (int i = ty; i < 32; i += 8)
            w2h[(size_t)(n0 + i) * Ed + k0 + tx] = __float2half_rn(t[tx][i]);
    } else {
        if (tid < 5) cnt[tid] = 0;
        __syncthreads();
        {
            const unsigned char* m8 = (const unsigned char*)mask;
            int loc[5] = {0, 0, 0, 0, 0};
            for (int i = tid; i < 16384; i += 256) {
                unsigned char v = m8[i];
                if (v) { loc[i & 3]++; if (v != 1) loc[4]++; }
            }
#pragma unroll
            for (int j = 0; j < 5; j++) if (loc[j]) atomicAdd(&cnt[j], loc[j]);
        }
        __syncthreads();
        int mode;
        {
            int c0 = cnt[0], c1 = cnt[1], c2 = cnt[2], c3 = cnt[3], weird = cnt[4];
            if (c1 == 0 && c2 == 0 && c3 == 0) mode = 1;
            else if (c0 == 0 && c1 == 0)       mode = 2;
            else if (weird > 0)                mode = 3;
            else                               mode = 0;
        }
        int w = (bz - TRF_BLKS) * 256 + tid;
        unsigned long long bits = 0;
        if (mode == 0) {
            const uint4* p = (const uint4*)((const unsigned char*)mask + (size_t)w * 64);
#pragma unroll
            for (int i = 0; i < 4; i++) {
                uint4 v = p[i];
                uint32_t ws[4] = {v.x, v.y, v.z, v.w};
#pragma unroll
                for (int j = 0; j < 4; j++)
#pragma unroll
                    for (int bq = 0; bq < 4; bq++)
                        if ((ws[j] >> (8 * bq)) & 0xFFu)
                            bits |= 1ull << (i * 16 + j * 4 + bq);
            }
        } else if (mode == 1 || mode == 2) {
            const uint4* p = (const uint4*)((const uint32_t*)mask + (size_t)w * 64);
#pragma unroll
            for (int i = 0; i < 16; i++) {
                uint4 v = p[i];
                if (v.x) bits |= 1ull << (i * 4 + 0);
                if (v.y) bits |= 1ull << (i * 4 + 1);
                if (v.z) bits |= 1ull << (i * 4 + 2);
                if (v.w) bits |= 1ull << (i * 4 + 3);
            }
        } else {
            const uint4* p = (const uint4*)((const unsigned short*)mask + (size_t)w * 64);
#pragma unroll
            for (int i = 0; i < 8; i++) {
                uint4 v = p[i];
                uint32_t ws[4] = {v.x, v.y, v.z, v.w};
#pragma unroll
                for (int j = 0; j < 4; j++) {
                    if (ws[j] & 0xFFFFu) bits |= 1ull << (i * 8 + j * 2);
                    if (ws[j] >> 16)     bits |= 1ull << (i * 8 + j * 2 + 1);
                }
            }
        }
        mbits[w] = bits;
    }
}

// ---------------- fp16 mma.sync GEMM: 128x128, 3-stage, 1 sync (R11 best) ---
#define GLD 40
#define GBK 32
#define GSTGB (128 * GLD * 2)            // 10240
#define GEMM_SMEM (6 * GSTGB)            // 61440

template<int MODE>
__global__ __launch_bounds__(256, 2)
void hgemm_k(const __half* __restrict__ A, const __half* __restrict__ Bt,
             const float* __restrict__ bias, float* __restrict__ C,
             __half* __restrict__ qh2, __half* __restrict__ kh2,
             __half* __restrict__ vh, int N, int K)
{
    extern __shared__ char gsm[];
    const uint32_t as_base = smem_u32(gsm);
    const uint32_t bs_base = as_base + 3 * GSTGB;

    const int tid = threadIdx.x;
    const int warp = tid >> 5, lane = tid & 31;
    const int gid = lane >> 2, tig = lane & 3;
    const int lr = lane & 7, lq = lane >> 3;
    const int m0 = blockIdx.y * 128, n0 = blockIdx.x * 128;
    const int wm0 = (warp & 3) * 32;
    const int wn0 = (warp >> 2) * 64;

    const __half* Ab = A + (size_t)m0 * K;
    const __half* Bb = Bt + (size_t)n0 * K;

    float acc[2][8][4];
#pragma unroll
    for (int i = 0; i < 2; i++)
#pragma unroll
        for (int j = 0; j < 8; j++)
#pragma unroll
            for (int r = 0; r < 4; r++) acc[i][j][r] = 0.f;

    const int lr0 = tid >> 2,          lc0 = (tid & 3) * 8;
    const int lr1 = (tid + 256) >> 2,  lc1 = (tid & 3) * 8;

    const int NS = K / GBK;   // 32

#pragma unroll
    for (int ps = 0; ps < 2; ps++) {
        uint32_t asb = as_base + ps * GSTGB;
        uint32_t bsb = bs_base + ps * GSTGB;
        int kb = ps * GBK;
        cp_async16(asb + (lr0 * GLD + lc0) * 2, Ab + (size_t)lr0 * K + kb + lc0);
        cp_async16(asb + (lr1 * GLD + lc1) * 2, Ab + (size_t)lr1 * K + kb + lc1);
        cp_async16(bsb + (lr0 * GLD + lc0) * 2, Bb + (size_t)lr0 * K + kb + lc0);
        cp_async16(bsb + (lr1 * GLD + lc1) * 2, Bb + (size_t)lr1 * K + kb + lc1);
        CP_COMMIT();
    }

    const int a_row_off = (lq & 1) * 8 + lr;
    const int a_col_off = (lq >> 1) * 8;
    const int b_row_off = (lq >> 1) * 8 + lr;
    const int b_col_off = (lq & 1) * 8;

    for (int s = 0; s < NS; ++s) {
        if (s == NS - 1) { CP_WAIT(0); } else { CP_WAIT(1); }
        __syncthreads();
        if (s + 2 < NS) {
            int st = (s + 2) % 3;
            int kb = (s + 2) * GBK;
            uint32_t asb = as_base + st * GSTGB;
            uint32_t bsb = bs_base + st * GSTGB;
            cp_async16(asb + (lr0 * GLD + lc0) * 2, Ab + (size_t)lr0 * K + kb + lc0);
            cp_async16(asb + (lr1 * GLD + lc1) * 2, Ab + (size_t)lr1 * K + kb + lc1);
            cp_async16(bsb + (lr0 * GLD + lc0) * 2, Bb + (size_t)lr0 * K + kb + lc0);
            cp_async16(bsb + (lr1 * GLD + lc1) * 2, Bb + (size_t)lr1 * K + kb + lc1);
            CP_COMMIT();
        }
        int cs = s % 3;
        uint32_t asb = as_base + cs * GSTGB;
        uint32_t bsb = bs_base + cs * GSTGB;
#pragma unroll
        for (int kk = 0; kk < GBK; kk += 16) {
            uint32_t afr[2][4];
#pragma unroll
            for (int i = 0; i < 2; i++) {
                uint32_t addr = asb + ((wm0 + 16 * i + a_row_off) * GLD + kk + a_col_off) * 2;
                LDM_X4(afr[i][0], afr[i][1], afr[i][2], afr[i][3], addr);
            }
            uint32_t bfr[8][2];
#pragma unroll
            for (int jj = 0; jj < 8; jj += 2) {
                uint32_t addr = bsb + ((wn0 + 8 * jj + b_row_off) * GLD + kk + b_col_off) * 2;
                LDM_X4(bfr[jj][0], bfr[jj][1], bfr[jj + 1][0], bfr[jj + 1][1], addr);
            }
#pragma unroll
            for (int j = 0; j < 8; j++) {
                mma_f16(acc[0][j], afr[0], bfr[j][0], bfr[j][1]);
                mma_f16(acc[1][j], afr[1], bfr[j][0], bfr[j][1]);
            }
        }
    }

#pragma unroll
    for (int i = 0; i < 2; i++) {
        int row = m0 + wm0 + 16 * i + gid;
#pragma unroll
        for (int j = 0; j < 8; j++) {
            int col = n0 + wn0 + 8 * j + 2 * tig;
            float2 bv = *(const float2*)&bias[col];
            float v00 = acc[i][j][0] + bv.x, v01 = acc[i][j][1] + bv.y;
            float v10 = acc[i][j][2] + bv.x, v11 = acc[i][j][3] + bv.y;
            if (MODE == 0) {
                float2 o0, o1;
                o0.x = v00; o0.y = v01; o1.x = v10; o1.y = v11;
                *(float2*)&C[(size_t)row * N + col]       = o0;
                *(float2*)&C[(size_t)(row + 8) * N + col] = o1;
            } else {
                int lc = col & 1023;
                if (col < Ed) {
                    *(uint32_t*)&qh2[(size_t)row * Ed + lc] =
                        pack_h2(v00 * QSCALE, v01 * QSCALE);
                    *(uint32_t*)&qh2[(size_t)(row + 8) * Ed + lc] =
                        pack_h2(v10 * QSCALE, v11 * QSCALE);
                } else if (col < 2 * Ed) {
                    *(uint32_t*)&kh2[(size_t)row * Ed + lc]       = pack_h2(v00, v01);
                    *(uint32_t*)&kh2[(size_t)(row + 8) * Ed + lc] = pack_h2(v10, v11);
                } else {
                    *(uint32_t*)&vh[(size_t)row * Ed + lc]       = pack_h2(v00, v01);
                    *(uint32_t*)&vh[(size_t)(row + 8) * Ed + lc] = pack_h2(v10, v11);
                }
            }
        }
    }
}

// ---------------- fp16 flash attention v8: 256-row q-tile, 32 rows/warp -----
// Halves K/V fragment reload amplification (8x -> 4x per unit work).
#define LK 72
#define KH_BYTES (64 * LK * 2)               // 9216
#define QH_BYTES (256 * LK * 2)              // 36864
#define AT_SMEM (QH_BYTES + 6 * KH_BYTES)    // 92160

__global__ __launch_bounds__(256, 1)
void attention_f16_kernel(const __half* __restrict__ qh2,
                          const __half* __restrict__ kh2,
                          const __half* __restrict__ vh,
                          const unsigned long long* __restrict__ mbits,
                          __half* __restrict__ ctxh) {
    extern __shared__ char asmem[];
    const uint32_t qh_smb = smem_u32(asmem);
    const uint32_t kh_smb = qh_smb + QH_BYTES;
    const uint32_t vs_smb = kh_smb + 3 * KH_BYTES;
    const __half* QHs = (const __half*)asmem;

    const int qt = blockIdx.x, bh = blockIdx.y;
    const int b = bh >> 4, h = bh & 15;
    const int tid = threadIdx.x, lane = tid & 31, warp = tid >> 5;
    const int gid = lane >> 2, tig = lane & 3;
    const int lr = lane & 7, lq = lane >> 3;
    const int q0 = qt * 256, hoff = h * Dh;
    const size_t bS = (size_t)b * Sq;
    const int wrow = warp * 32;   // 32 q-rows per warp

    const uint32_t k_ldm_off = (lr * LK + 8 * lq) * 2;
    const uint32_t v_ldm_off = (((lq & 1) * 8 + lr) * LK + (lq >> 1) * 8) * 2;

    const int NT = Sq / 64;   // 32

    // prologue: group1 = {Q(256 rows), K0, V0}; group2 = {K1, V1}
#pragma unroll
    for (int t = 0; t < 8; t++) {
        int idx = tid + t * 256;
        int r = idx >> 3, c = (idx & 7) * 8;
        cp_async16(qh_smb + (r * LK + c) * 2, qh2 + (bS + q0 + r) * Ed + hoff + c);
    }
#pragma unroll
    for (int t = 0; t < 2; t++) {
        int idx = tid + t * 256;
        int r = idx >> 3, c = (idx & 7) * 8;
        cp_async16(kh_smb + (r * LK + c) * 2, kh2 + (bS + r) * Ed + hoff + c);
        cp_async16(vs_smb + (r * LK + c) * 2, vh  + (bS + r) * Ed + hoff + c);
    }
    CP_COMMIT();
#pragma unroll
    for (int t = 0; t < 2; t++) {
        int idx = tid + t * 256;
        int r = idx >> 3, c = (idx & 7) * 8;
        cp_async16(kh_smb + KH_BYTES + (r * LK + c) * 2, kh2 + (bS + 64 + r) * Ed + hoff + c);
        cp_async16(vs_smb + KH_BYTES + (r * LK + c) * 2, vh  + (bS + 64 + r) * Ed + hoff + c);
    }
    CP_COMMIT();

    CP_WAIT(1);
    __syncthreads();

    // Q fragments for two 16-row m-groups (register-resident)
    uint32_t qf[2][4][4];
#pragma unroll
    for (int mg = 0; mg < 2; mg++) {
        int r0 = wrow + mg * 16 + gid, r1 = r0 + 8;
#pragma unroll
        for (int kc = 0; kc < 4; kc++) {
            qf[mg][kc][0] = *(const uint32_t*)&QHs[r0 * LK + 16 * kc + 2 * tig];
            qf[mg][kc][1] = *(const uint32_t*)&QHs[r1 * LK + 16 * kc + 2 * tig];
            qf[mg][kc][2] = *(const uint32_t*)&QHs[r0 * LK + 16 * kc + 8 + 2 * tig];
            qf[mg][kc][3] = *(const uint32_t*)&QHs[r1 * LK + 16 * kc + 8 + 2 * tig];
        }
    }

    const unsigned long long* mr[2][2];
#pragma unroll
    for (int mg = 0; mg < 2; mg++) {
        mr[mg][0] = mbits + (bS + q0 + wrow + mg * 16 + gid) * (Sq / 64);
        mr[mg][1] = mbits + (bS + q0 + wrow + mg * 16 + gid + 8) * (Sq / 64);
    }

    float oacc[2][8][4], osum[2][4];
#pragma unroll
    for (int mg = 0; mg < 2; mg++) {
#pragma unroll
        for (int j = 0; j < 8; j++)
#pragma unroll
            for (int r = 0; r < 4; r++) oacc[mg][j][r] = 0.f;
#pragma unroll
        for (int r = 0; r < 4; r++) osum[mg][r] = 0.f;
    }

    const uint32_t ONES = 0x3C003C00u;

    for (int kt = 0; kt < NT; kt++) {
        if (kt > 0) {
            if (kt == NT - 1) { CP_WAIT(0); } else { CP_WAIT(1); }
            __syncthreads();
        }
        if (kt + 2 < NT) {
            int st = (kt + 2) % 3;
            int k0n = (kt + 2) * 64;
            uint32_t kb = kh_smb + st * KH_BYTES;
            uint32_t vb = vs_smb + st * KH_BYTES;
#pragma unroll
            for (int t = 0; t < 2; t++) {
                int idx = tid + t * 256;
                int r = idx >> 3, c = (idx & 7) * 8;
                cp_async16(kb + (r * LK + c) * 2, kh2 + (bS + k0n + r) * Ed + hoff + c);
                cp_async16(vb + (r * LK + c) * 2, vh  + (bS + k0n + r) * Ed + hoff + c);
            }
            CP_COMMIT();
        }
        const int buf = kt % 3;
        const uint32_t kbase = kh_smb + buf * KH_BYTES + k_ldm_off;
        const uint32_t vbase = vs_smb + buf * KH_BYTES + v_ldm_off;

        // QK^T: one K-fragment load feeds both m-groups (2x reuse)
        float sc[2][8][4];
#pragma unroll
        for (int mg = 0; mg < 2; mg++)
#pragma unroll
            for (int j = 0; j < 8; j++)
#pragma unroll
                for (int r = 0; r < 4; r++) sc[mg][j][r] = 0.f;
#pragma unroll
        for (int j = 0; j < 8; j++) {
            uint32_t kaddr = kbase + j * (8 * LK * 2);
            uint32_t k0r, k1r, k2r, k3r, k4r, k5r, k6r, k7r;
            LDM_X4(k0r, k1r, k2r, k3r, kaddr);
            LDM_X4(k4r, k5r, k6r, k7r, kaddr + 64);
            mma_f16(sc[0][j], qf[0][0], k0r, k1r);
            mma_f16(sc[0][j], qf[0][1], k2r, k3r);
            mma_f16(sc[0][j], qf[0][2], k4r, k5r);
            mma_f16(sc[0][j], qf[0][3], k6r, k7r);
            mma_f16(sc[1][j], qf[1][0], k0r, k1r);
            mma_f16(sc[1][j], qf[1][1], k2r, k3r);
            mma_f16(sc[1][j], qf[1][2], k4r, k5r);
            mma_f16(sc[1][j], qf[1][3], k6r, k7r);
        }

        // mask quirk + clamp + fp16 pack + 2^y
        uint32_t pp[2][8][2];
#pragma unroll
        for (int mg = 0; mg < 2; mg++) {
            unsigned long long mb0 = mr[mg][0][kt];
            unsigned long long mb1 = mr[mg][1][kt];
#pragma unroll
            for (int j = 0; j < 8; j++) {
                int col = 8 * j + 2 * tig;
                float y00 = ((mb0 >> col) & 1)       ? MASKC : fminf(sc[mg][j][0], 14.f);
                float y01 = ((mb0 >> (col + 1)) & 1) ? MASKC : fminf(sc[mg][j][1], 14.f);
                float y10 = ((mb1 >> col) & 1)       ? MASKC : fminf(sc[mg][j][2], 14.f);
                float y11 = ((mb1 >> (col + 1)) & 1) ? MASKC : fminf(sc[mg][j][3], 14.f);
                pp[mg][j][0] = ex2_h2(pack_h2(y00, y01));
                pp[mg][j][1] = ex2_h2(pack_h2(y10, y11));
            }
        }

        // PV + denominator: one V-fragment load feeds both m-groups
#pragma unroll
        for (int kc = 0; kc < 4; kc++) {
            uint32_t a0[4] = { pp[0][2 * kc][0], pp[0][2 * kc][1],
                               pp[0][2 * kc + 1][0], pp[0][2 * kc + 1][1] };
            uint32_t a1[4] = { pp[1][2 * kc][0], pp[1][2 * kc][1],
                               pp[1][2 * kc + 1][0], pp[1][2 * kc + 1][1] };
            mma_f16(osum[0], a0, ONES, ONES);
            mma_f16(osum[1], a1, ONES, ONES);
#pragma unroll
            for (int jj = 0; jj < 8; jj += 2) {
                uint32_t b0, b1, b2, b3;
                LDM_X4_T(b0, b1, b2, b3,
                         vbase + (16 * kc * LK + 8 * jj) * 2);
                mma_f16(oacc[0][jj],     a0, b0, b1);
                mma_f16(oacc[0][jj + 1], a0, b2, b3);
                mma_f16(oacc[1][jj],     a1, b0, b1);
                mma_f16(oacc[1][jj + 1], a1, b2, b3);
            }
        }
    }

    // epilogue: normalize per m-group, write ctx fp16
#pragma unroll
    for (int mg = 0; mg < 2; mg++) {
        float inv0 = 1.f / osum[mg][0], inv1 = 1.f / osum[mg][2];
        const size_t row0 = bS + q0 + wrow + mg * 16 + gid;
#pragma unroll
        for (int j = 0; j < 8; j++) {
            int col = hoff + 8 * j + 2 * tig;
            *(uint32_t*)&ctxh[row0 * Ed + col] =
                pack_h2(oacc[mg][j][0] * inv0, oacc[mg][j][1] * inv0);
            *(uint32_t*)&ctxh[(row0 + 8) * Ed + col] =
                pack_h2(oacc[mg][j][2] * inv1, oacc[mg][j][3] * inv1);
        }
    }
}

// ---------------- launcher with two-stream capture fork ----------------
extern "C" void kernel_launch(void* const* d_in, const int* in_sizes, int n_in,
                              void* d_out, int out_size) {
    const float* x        = (const float*)d_in[0];
    const void*  amask    = d_in[1];
    const float* w_kernel = (const float*)d_in[2];
    const float* w_bias   = (const float*)d_in[3];
    const float* fc_kernel= (const float*)d_in[4];
    const float* fc_bias  = (const float*)d_in[5];
    float* out = (float*)d_out;

    __half *xh, *wh, *w2h, *qh2, *kh2, *vh, *ctxh;
    unsigned long long* mbits;
    cudaGetSymbolAddress((void**)&xh,   g_xh);
    cudaGetSymbolAddress((void**)&wh,   g_wh);
    cudaGetSymbolAddress((void**)&w2h,  g_w2h);
    cudaGetSymbolAddress((void**)&qh2,  g_qh2);
    cudaGetSymbolAddress((void**)&kh2,  g_kh2);
    cudaGetSymbolAddress((void**)&vh,   g_vh);
    cudaGetSymbolAddress((void**)&ctxh, g_ctxh);
    cudaGetSymbolAddress((void**)&mbits, g_mbits);

    static cudaStream_t s2 = nullptr;
    static cudaEvent_t evFork = nullptr, evJoin = nullptr;
    if (s2 == nullptr) {
        cudaStreamCreateWithFlags(&s2, cudaStreamNonBlocking);
        cudaEventCreateWithFlags(&evFork, cudaEventDisableTiming);
        cudaEventCreateWithFlags(&evJoin, cudaEventDisableTiming);
        cudaFuncSetAttribute(hgemm_k<1>, cudaFuncAttributeMaxDynamicSharedMemorySize, GEMM_SMEM);
        cudaFuncSetAttribute(hgemm_k<0>, cudaFuncAttributeMaxDynamicSharedMemorySize, GEMM_SMEM);
        cudaFuncSetAttribute(attention_f16_kernel,
                             cudaFuncAttributeMaxDynamicSharedMemorySize, AT_SMEM);
    }

    // fork: fc-transpose + mask-pack overlapped with prep_xw + hgemm1
    cudaEventRecord(evFork, 0);
    cudaStreamWaitEvent(s2, evFork, 0);
    prep_fcmask_kernel<<<PFM_BLKS, 256, 0, s2>>>(fc_kernel, amask, w2h, mbits);
    cudaEventRecord(evJoin, s2);

    prep_xw_kernel<<<PXW_BLKS, 256>>>((const float4*)x, w_kernel, (uint2*)xh, wh);

    hgemm_k<1><<<dim3(E3 / 128, Mrows / 128), 256, GEMM_SMEM>>>(
        xh, wh, w_bias, nullptr, qh2, kh2, vh, E3, Ed);

    cudaStreamWaitEvent(0, evJoin, 0);

    {
        dim3 grid(Sq / 256, Bz * Hh);
        attention_f16_kernel<<<grid, 256, AT_SMEM>>>(qh2, kh2, vh, mbits, ctxh);
    }

    hgemm_k<0><<<dim3(Ed / 128, Mrows / 128), 256, GEMM_SMEM>>>(
        ctxh, w2h, fc_bias, out, nullptr, nullptr, nullptr, Ed, Ed);
}